// round 4
// baseline (speedup 1.0000x reference)
#include <cuda_runtime.h>
#include <cuda_bf16.h>
#include <math.h>

// ---------------------------------------------------------------------------
// FixedEmbedderNN — fully collapsed to THREE table gathers (zero runtime GEMM):
//   z0       = gather(T0,P0) + c0                      -> mu0, inv0
//   z1       = (gather(T1,P1) + c0M1 - mu0*u1)*inv0 + c1   -> mu1, inv1
//   out      = ((gather(T2,P2) + c0M1o - mu0*u1o)*inv0 + c1Mo - mu1*uo)*inv1 + co
// where T1 = T0@M1, T2 = T0@(M1@Mo), M1 = diag(g0)(W1[1]W2[1]), Mo = diag(g1)W_out,
// u* are column sums, c* folded biases. Exact fp32 algebra (reassociation only).
// ---------------------------------------------------------------------------

#define NCAT 20
#define NNUM 20
#define LN_EPS 1e-5f

// -------- device-global scratch (no allocations allowed) --------
__device__ float g_A[1280 * 256];      // W_in @ W1[0]
__device__ float g_Wfold[1280 * 128];  // (W_in W1[0]) W2[0]
__device__ float g_B1[128 * 128];      // W1[1] @ W2[1]
__device__ float g_M1[128 * 128];      // diag(g0) B1
__device__ float g_Mo[128 * 128];      // diag(g1) W_out
__device__ float g_M1o[128 * 128];     // M1 @ Mo
__device__ float g_T0[1024 * 128];     // per-(f,code) z0-space vectors (1000 used, padded)
__device__ float g_T1[1024 * 128];     // T0 @ M1
__device__ float g_T2[1024 * 128];     // T0 @ M1o
__device__ float g_P0[32 * 128];       // numeric slopes in z0 space (20 used, padded)
__device__ float g_P1[32 * 128];
__device__ float g_P2[32 * 128];
__device__ float g_c0[128], g_c1[128], g_co[128];
__device__ float g_c0M1[128], g_c0M1o[128], g_c1Mo[128];
__device__ float g_u1[128], g_u1o[128], g_uo[128];

// ------------------------- generic tiled SGEMM (precompute only) -----------
__global__ void sgemm32(const float* __restrict__ A, const float* __restrict__ B,
                        float* __restrict__ C, int M, int N, int K) {
    __shared__ float As[32][33];
    __shared__ float Bs[32][33];
    int bx = blockIdx.x * 32;
    int by = blockIdx.y * 32;
    int tx = threadIdx.x & 31;
    int ty = threadIdx.x >> 5;  // 0..7
    float acc[4] = {0.f, 0.f, 0.f, 0.f};
    for (int k0 = 0; k0 < K; k0 += 32) {
        #pragma unroll
        for (int i = 0; i < 4; i++) {
            As[ty + 8 * i][tx] = A[(size_t)(bx + ty + 8 * i) * K + k0 + tx];
            Bs[ty + 8 * i][tx] = B[(size_t)(k0 + ty + 8 * i) * N + by + tx];
        }
        __syncthreads();
        #pragma unroll
        for (int kk = 0; kk < 32; kk++) {
            float b = Bs[kk][tx];
            #pragma unroll
            for (int i = 0; i < 4; i++) acc[i] += As[ty + 8 * i][kk] * b;
        }
        __syncthreads();
    }
    #pragma unroll
    for (int i = 0; i < 4; i++) C[(size_t)(bx + ty + 8 * i) * N + by + tx] = acc[i];
}

// ------------------------- table builders ----------------------------------
__global__ void build_T(const float* __restrict__ emb) {
    int fc = blockIdx.x;  // f*50 + c
    int f = fc / 50;
    int j = threadIdx.x;
    __shared__ float e[32];
    if (j < 32) e[j] = emb[fc * 32 + j];
    __syncthreads();
    float acc = 0.f;
    #pragma unroll
    for (int i = 0; i < 32; i++) acc += e[i] * g_Wfold[(f * 32 + i) * 128 + j];
    g_T0[fc * 128 + j] = acc;
}

__global__ void build_P(const float* __restrict__ W_num) {
    int f = blockIdx.x;
    int j = threadIdx.x;
    __shared__ float w[32];
    if (j < 32) w[j] = W_num[f * 32 + j];
    __syncthreads();
    float acc = 0.f;
    #pragma unroll
    for (int i = 0; i < 32; i++) acc += w[i] * g_Wfold[(640 + f * 32 + i) * 128 + j];
    g_P0[f * 128 + j] = acc;
}

__global__ void scaleM(const float* __restrict__ ln_g, const float* __restrict__ W_out) {
    int k = blockIdx.x;
    int j = threadIdx.x;
    g_M1[k * 128 + j] = ln_g[k] * g_B1[k * 128 + j];
    g_Mo[k * 128 + j] = ln_g[128 + k] * W_out[k * 128 + j];
}

// ------------------------- folded bias / colsum vectors ---------------------
__global__ void build_vectors(const float* __restrict__ b_num, const float* __restrict__ b_in,
                              const float* __restrict__ W1, const float* __restrict__ b1,
                              const float* __restrict__ W2, const float* __restrict__ b2,
                              const float* __restrict__ ln_b, const float* __restrict__ W_out,
                              const float* __restrict__ b_out) {
    __shared__ float u[256];
    __shared__ float c0s[128];
    __shared__ float c1s[128];
    int j = threadIdx.x;  // 128 threads
    for (int m = j; m < 256; m += 128) {
        float s = b1[m];
        for (int k = 0; k < 128; k++) s += b_in[k] * W1[k * 256 + m];
        u[m] = s;
    }
    __syncthreads();
    float c0 = b2[j];
    for (int m = 0; m < 256; m++) c0 += u[m] * W2[m * 128 + j];
    for (int i = 0; i < 640; i++) c0 += b_num[i] * g_Wfold[(640 + i) * 128 + j];
    g_c0[j] = c0;
    c0s[j] = c0;
    float c1 = b2[128 + j];
    for (int k = 0; k < 128; k++) c1 += ln_b[k] * g_B1[k * 128 + j];
    for (int m = 0; m < 256; m++) c1 += b1[256 + m] * W2[(256 + m) * 128 + j];
    g_c1[j] = c1;
    c1s[j] = c1;
    float co = b_out[j];
    for (int k = 0; k < 128; k++) co += ln_b[128 + k] * W_out[k * 128 + j];
    g_co[j] = co;
    __syncthreads();
    float u1 = 0.f, u1o = 0.f, uo = 0.f, cm1 = 0.f, cm1o = 0.f, c1mo = 0.f;
    for (int k = 0; k < 128; k++) {
        float m1 = g_M1[k * 128 + j];
        float m1o = g_M1o[k * 128 + j];
        float mo = g_Mo[k * 128 + j];
        u1 += m1;
        u1o += m1o;
        uo += mo;
        cm1 = fmaf(c0s[k], m1, cm1);
        cm1o = fmaf(c0s[k], m1o, cm1o);
        c1mo = fmaf(c1s[k], mo, c1mo);
    }
    g_u1[j] = u1;
    g_u1o[j] = u1o;
    g_uo[j] = uo;
    g_c0M1[j] = cm1;
    g_c0M1o[j] = cm1o;
    g_c1Mo[j] = c1mo;
}

// ------------------------- main fused kernel --------------------------------
#define TROWS 64

__device__ __forceinline__ void gather_phase(const float* __restrict__ T,
                                             const float* __restrict__ P, float4 acc[8],
                                             const int* __restrict__ codes,
                                             const float* __restrict__ nums, int j4, int w) {
    #pragma unroll 2
    for (int f = 0; f < NCAT; f++) {
        const float4 pv = __ldg((const float4*)&P[f * 128 + 4 * j4]);
        const float* Tf = T + f * 50 * 128;
        #pragma unroll
        for (int s = 0; s < 8; s++) {
            const int r = 8 * s + w;
            const int c = codes[r * NCAT + f];
            const float v = nums[r * NNUM + f];
            const float4 tv = __ldg((const float4*)&Tf[c * 128 + 4 * j4]);
            acc[s].x = fmaf(v, pv.x, acc[s].x + tv.x);
            acc[s].y = fmaf(v, pv.y, acc[s].y + tv.y);
            acc[s].z = fmaf(v, pv.z, acc[s].z + tv.z);
            acc[s].w = fmaf(v, pv.w, acc[s].w + tv.w);
        }
    }
}

__device__ __forceinline__ void row_stats(const float4 a, float& mu, float& inv) {
    float s1 = a.x + a.y + a.z + a.w;
    float s2 = a.x * a.x + a.y * a.y + a.z * a.z + a.w * a.w;
    #pragma unroll
    for (int o = 16; o > 0; o >>= 1) {
        s1 += __shfl_xor_sync(0xffffffffu, s1, o);
        s2 += __shfl_xor_sync(0xffffffffu, s2, o);
    }
    mu = s1 * (1.f / 128.f);
    inv = rsqrtf(s2 * (1.f / 128.f) - mu * mu + LN_EPS);
}

__global__ __launch_bounds__(256) void main_kernel(const float* __restrict__ x,
                                                   float* __restrict__ out, int nrows) {
    __shared__ int codes[TROWS * NCAT];
    __shared__ float nums[TROWS * NNUM];

    const int t = threadIdx.x;
    const int rowbase = blockIdx.x * TROWS;

    for (int i = t; i < TROWS * 40; i += 256) {
        int r = i / 40, f = i % 40;
        int gr = rowbase + r;
        float v = (gr < nrows) ? x[(size_t)gr * 40 + f] : 0.f;
        if (f < NCAT) {
            int c = (int)v;
            c = c < 0 ? 0 : (c > 49 ? 49 : c);
            codes[r * NCAT + f] = c;
        } else {
            nums[r * NNUM + (f - NCAT)] = v;
        }
    }
    __syncthreads();

    const int j4 = t & 31;  // lane -> 4 cols
    const int w = t >> 5;   // warp -> rows 8s+w (whole row within one warp)
    float4 acc[8];
    float mu0[8], i0[8], mu1[8], i1[8];

    // ---- Phase A: z0 = gather(T0,P0) + c0 -> mu0, inv0 ----
    {
        const float4 cz = __ldg((const float4*)&g_c0[4 * j4]);
        #pragma unroll
        for (int s = 0; s < 8; s++) acc[s] = cz;
        gather_phase(g_T0, g_P0, acc, codes, nums, j4, w);
        #pragma unroll
        for (int s = 0; s < 8; s++) row_stats(acc[s], mu0[s], i0[s]);
    }

    // ---- Phase B: z1 = (gather(T1,P1) + c0M1 - mu0*u1)*inv0 + c1 -> mu1, inv1 ----
    {
        const float4 cz = __ldg((const float4*)&g_c0M1[4 * j4]);
        const float4 u1v = __ldg((const float4*)&g_u1[4 * j4]);
        const float4 c1v = __ldg((const float4*)&g_c1[4 * j4]);
        #pragma unroll
        for (int s = 0; s < 8; s++) acc[s] = cz;
        gather_phase(g_T1, g_P1, acc, codes, nums, j4, w);
        #pragma unroll
        for (int s = 0; s < 8; s++) {
            float4 z;
            z.x = fmaf(acc[s].x - mu0[s] * u1v.x, i0[s], c1v.x);
            z.y = fmaf(acc[s].y - mu0[s] * u1v.y, i0[s], c1v.y);
            z.z = fmaf(acc[s].z - mu0[s] * u1v.z, i0[s], c1v.z);
            z.w = fmaf(acc[s].w - mu0[s] * u1v.w, i0[s], c1v.w);
            row_stats(z, mu1[s], i1[s]);
        }
    }

    // ---- Phase C: out = ((gather(T2,P2)+c0M1o-mu0*u1o)*inv0 + c1Mo - mu1*uo)*inv1 + co ----
    {
        const float4 cz = __ldg((const float4*)&g_c0M1o[4 * j4]);
        const float4 u1ov = __ldg((const float4*)&g_u1o[4 * j4]);
        const float4 c1mov = __ldg((const float4*)&g_c1Mo[4 * j4]);
        const float4 uov = __ldg((const float4*)&g_uo[4 * j4]);
        const float4 cov = __ldg((const float4*)&g_co[4 * j4]);
        #pragma unroll
        for (int s = 0; s < 8; s++) acc[s] = cz;
        gather_phase(g_T2, g_P2, acc, codes, nums, j4, w);
        #pragma unroll
        for (int s = 0; s < 8; s++) {
            int gr = rowbase + 8 * s + w;
            float4 zm;  // z1 @ Mo
            zm.x = fmaf(acc[s].x - mu0[s] * u1ov.x, i0[s], c1mov.x);
            zm.y = fmaf(acc[s].y - mu0[s] * u1ov.y, i0[s], c1mov.y);
            zm.z = fmaf(acc[s].z - mu0[s] * u1ov.z, i0[s], c1mov.z);
            zm.w = fmaf(acc[s].w - mu0[s] * u1ov.w, i0[s], c1mov.w);
            float4 o;
            o.x = fmaf(zm.x - mu1[s] * uov.x, i1[s], cov.x);
            o.y = fmaf(zm.y - mu1[s] * uov.y, i1[s], cov.y);
            o.z = fmaf(zm.z - mu1[s] * uov.z, i1[s], cov.z);
            o.w = fmaf(zm.w - mu1[s] * uov.w, i1[s], cov.w);
            if (gr < nrows) *(float4*)&out[(size_t)gr * 128 + 4 * j4] = o;
        }
    }
}

// ---------------------------------------------------------------------------
extern "C" void kernel_launch(void* const* d_in, const int* in_sizes, int n_in,
                              void* d_out, int out_size) {
    const float* x     = (const float*)d_in[0];
    const float* emb   = (const float*)d_in[1];
    const float* W_num = (const float*)d_in[2];
    const float* b_num = (const float*)d_in[3];
    const float* W_in  = (const float*)d_in[4];
    const float* b_in  = (const float*)d_in[5];
    const float* W1    = (const float*)d_in[6];
    const float* b1    = (const float*)d_in[7];
    const float* W2    = (const float*)d_in[8];
    const float* b2    = (const float*)d_in[9];
    const float* ln_g  = (const float*)d_in[10];
    const float* ln_b  = (const float*)d_in[11];
    const float* W_out = (const float*)d_in[12];
    const float* b_out = (const float*)d_in[13];
    float* out = (float*)d_out;

    int nrows = in_sizes[0] / 40;
    int ntiles = (nrows + TROWS - 1) / TROWS;

    float *pA, *pWfold, *pB1, *pM1, *pMo, *pM1o, *pT0, *pT1, *pT2, *pP0, *pP1, *pP2;
    cudaGetSymbolAddress((void**)&pA, g_A);
    cudaGetSymbolAddress((void**)&pWfold, g_Wfold);
    cudaGetSymbolAddress((void**)&pB1, g_B1);
    cudaGetSymbolAddress((void**)&pM1, g_M1);
    cudaGetSymbolAddress((void**)&pMo, g_Mo);
    cudaGetSymbolAddress((void**)&pM1o, g_M1o);
    cudaGetSymbolAddress((void**)&pT0, g_T0);
    cudaGetSymbolAddress((void**)&pT1, g_T1);
    cudaGetSymbolAddress((void**)&pT2, g_T2);
    cudaGetSymbolAddress((void**)&pP0, g_P0);
    cudaGetSymbolAddress((void**)&pP1, g_P1);
    cudaGetSymbolAddress((void**)&pP2, g_P2);

    // precompute chain (graph-ordered on default stream)
    sgemm32<<<dim3(40, 8), 256>>>(W_in, W1, pA, 1280, 256, 128);                 // A = Win W1[0]
    sgemm32<<<dim3(40, 4), 256>>>(pA, W2, pWfold, 1280, 128, 256);               // Wfold
    sgemm32<<<dim3(4, 4), 256>>>(W1 + 128 * 256, W2 + 256 * 128, pB1, 128, 128, 256);  // B1
    scaleM<<<128, 128>>>(ln_g, W_out);                                           // M1, Mo
    sgemm32<<<dim3(4, 4), 256>>>(pM1, pMo, pM1o, 128, 128, 128);                 // M1o
    build_T<<<NCAT * 50, 128>>>(emb);                                            // T0
    build_P<<<NNUM, 128>>>(W_num);                                               // P0
    sgemm32<<<dim3(32, 4), 256>>>(pT0, pM1, pT1, 1024, 128, 128);                // T1
    sgemm32<<<dim3(32, 4), 256>>>(pT0, pM1o, pT2, 1024, 128, 128);               // T2
    sgemm32<<<dim3(1, 4), 256>>>(pP0, pM1, pP1, 32, 128, 128);                   // P1
    sgemm32<<<dim3(1, 4), 256>>>(pP0, pM1o, pP2, 32, 128, 128);                  // P2
    build_vectors<<<1, 128>>>(b_num, b_in, W1, b1, W2, b2, ln_b, W_out, b_out);

    main_kernel<<<ntiles, 256>>>(x, out, nrows);
}

// round 5
// speedup vs baseline: 1.2020x; 1.2020x over previous
#include <cuda_runtime.h>
#include <cuda_bf16.h>
#include <math.h>

// ---------------------------------------------------------------------------
// FixedEmbedderNN — collapsed network (R2 structure) + packed f32x2 math:
//   z0 = gather(T0,P0) + c0 ; zn0 = LN(z0)
//   z1 = zn0 @ M1 + c1      ; zn1 = LN(z1)
//   out = zn1 @ Mo + co
// GEMMs & gather use fma.rn.f32x2 (2 MAC per issue slot).
// ---------------------------------------------------------------------------

#define NCAT 20
#define NNUM 20
#define LN_EPS 1e-5f

// -------- device-global scratch --------
__device__ float g_A[1280 * 256];      // W_in @ W1[0]
__device__ float g_Wfold[1280 * 128];  // (W_in W1[0]) W2[0]
__device__ float g_B1[128 * 128];      // W1[1] @ W2[1]
__device__ float g_T[1024 * 128];      // per-(f,code) z0-space vectors
__device__ float g_P[32 * 128];        // numeric slopes in z0 space
__device__ float g_M1[128 * 128];      // diag(g0) B1
__device__ float g_Mo[128 * 128];      // diag(g1) W_out
__device__ float g_c0[128], g_c1[128], g_co[128];

// -------- f32x2 helpers --------
typedef unsigned long long u64p;
__device__ __forceinline__ u64p pk2(float a, float b) {
    u64p r; asm("mov.b64 %0, {%1, %2};" : "=l"(r) : "f"(a), "f"(b)); return r;
}
__device__ __forceinline__ void upk2(u64p p, float& x, float& y) {
    asm("mov.b64 {%0, %1}, %2;" : "=f"(x), "=f"(y) : "l"(p));
}
__device__ __forceinline__ u64p fma2(u64p a, u64p b, u64p c) {
    u64p d; asm("fma.rn.f32x2 %0, %1, %2, %3;" : "=l"(d) : "l"(a), "l"(b), "l"(c)); return d;
}
__device__ __forceinline__ u64p add2(u64p a, u64p b) {
    u64p d; asm("add.rn.f32x2 %0, %1, %2;" : "=l"(d) : "l"(a), "l"(b)); return d;
}

// ------------------------- generic tiled SGEMM (precompute only) -----------
__global__ void sgemm32(const float* __restrict__ A, const float* __restrict__ B,
                        float* __restrict__ C, int M, int N, int K) {
    __shared__ float As[32][33];
    __shared__ float Bs[32][33];
    int bx = blockIdx.x * 32;
    int by = blockIdx.y * 32;
    int tx = threadIdx.x & 31;
    int ty = threadIdx.x >> 5;
    float acc[4] = {0.f, 0.f, 0.f, 0.f};
    for (int k0 = 0; k0 < K; k0 += 32) {
        #pragma unroll
        for (int i = 0; i < 4; i++) {
            As[ty + 8 * i][tx] = A[(size_t)(bx + ty + 8 * i) * K + k0 + tx];
            Bs[ty + 8 * i][tx] = B[(size_t)(k0 + ty + 8 * i) * N + by + tx];
        }
        __syncthreads();
        #pragma unroll
        for (int kk = 0; kk < 32; kk++) {
            float b = Bs[kk][tx];
            #pragma unroll
            for (int i = 0; i < 4; i++) acc[i] += As[ty + 8 * i][kk] * b;
        }
        __syncthreads();
    }
    #pragma unroll
    for (int i = 0; i < 4; i++) C[(size_t)(bx + ty + 8 * i) * N + by + tx] = acc[i];
}

// ------------------------- table builders ----------------------------------
__global__ void build_T(const float* __restrict__ emb) {
    int fc = blockIdx.x;  // f*50 + c
    int f = fc / 50;
    int j = threadIdx.x;
    __shared__ float e[32];
    if (j < 32) e[j] = emb[fc * 32 + j];
    __syncthreads();
    float acc = 0.f;
    #pragma unroll
    for (int i = 0; i < 32; i++) acc += e[i] * g_Wfold[(f * 32 + i) * 128 + j];
    g_T[fc * 128 + j] = acc;
}

__global__ void build_P(const float* __restrict__ W_num) {
    int f = blockIdx.x;
    int j = threadIdx.x;
    __shared__ float w[32];
    if (j < 32) w[j] = W_num[f * 32 + j];
    __syncthreads();
    float acc = 0.f;
    #pragma unroll
    for (int i = 0; i < 32; i++) acc += w[i] * g_Wfold[(640 + f * 32 + i) * 128 + j];
    g_P[f * 128 + j] = acc;
}

__global__ void scaleM(const float* __restrict__ ln_g, const float* __restrict__ W_out) {
    int k = blockIdx.x;
    int j = threadIdx.x;
    g_M1[k * 128 + j] = ln_g[k] * g_B1[k * 128 + j];
    g_Mo[k * 128 + j] = ln_g[128 + k] * W_out[k * 128 + j];
}

__global__ void build_biases(const float* __restrict__ b_num, const float* __restrict__ b_in,
                             const float* __restrict__ W1, const float* __restrict__ b1,
                             const float* __restrict__ W2, const float* __restrict__ b2,
                             const float* __restrict__ ln_b, const float* __restrict__ W_out,
                             const float* __restrict__ b_out) {
    __shared__ float u[256];
    int j = threadIdx.x;  // 128 threads
    for (int m = j; m < 256; m += 128) {
        float s = b1[m];
        for (int k = 0; k < 128; k++) s += b_in[k] * W1[k * 256 + m];
        u[m] = s;
    }
    __syncthreads();
    float c0 = b2[j];
    for (int m = 0; m < 256; m++) c0 += u[m] * W2[m * 128 + j];
    for (int i = 0; i < 640; i++) c0 += b_num[i] * g_Wfold[(640 + i) * 128 + j];
    g_c0[j] = c0;
    float c1 = b2[128 + j];
    for (int k = 0; k < 128; k++) c1 += ln_b[k] * g_B1[k * 128 + j];
    for (int m = 0; m < 256; m++) c1 += b1[256 + m] * W2[(256 + m) * 128 + j];
    g_c1[j] = c1;
    float co = b_out[j];
    for (int k = 0; k < 128; k++) co += ln_b[128 + k] * W_out[k * 128 + j];
    g_co[j] = co;
}

// ------------------------- main fused kernel --------------------------------
#define TROWS 128
#define SP 132
#define SMEM_FLOATS (TROWS * SP + TROWS * NCAT + TROWS * NNUM)
#define SMEM_BYTES (SMEM_FLOATS * 4)

__global__ __launch_bounds__(256, 2) void main_kernel(const float* __restrict__ x,
                                                      float* __restrict__ out, int nrows) {
    extern __shared__ float sm[];
    float* S = sm;                                 // [128][SP]
    int* codes = (int*)(sm + TROWS * SP);          // [128][20]
    float* nums = (float*)(codes + TROWS * NCAT);  // [128][20]

    const int t = threadIdx.x;
    const int rowbase = blockIdx.x * TROWS;

    for (int i = t; i < TROWS * 40; i += 256) {
        int r = i / 40, f = i % 40;
        int gr = rowbase + r;
        float v = (gr < nrows) ? x[(size_t)gr * 40 + f] : 0.f;
        if (f < NCAT) {
            int c = (int)v;
            c = c < 0 ? 0 : (c > 49 ? 49 : c);
            codes[r * NCAT + f] = c;
        } else {
            nums[r * NNUM + (f - NCAT)] = v;
        }
    }
    __syncthreads();

    // ---- gather phase (packed f32x2): z0 in registers ----
    {
        const int j4 = t & 31;  // lane -> cols 4*j4..4*j4+3
        const int w = t >> 5;   // warp -> rows 8s+w
        ulonglong2 acc[16];
        {
            const ulonglong2 cz = *(const ulonglong2*)&g_c0[4 * j4];
            #pragma unroll
            for (int s = 0; s < 16; s++) acc[s] = cz;
        }
        #pragma unroll 2
        for (int f = 0; f < NCAT; f++) {
            const ulonglong2 pv = __ldg((const ulonglong2*)&g_P[f * 128 + 4 * j4]);
            const float* Tf = g_T + f * 50 * 128;
            #pragma unroll
            for (int s = 0; s < 16; s++) {
                const int r = 8 * s + w;
                const int c = codes[r * NCAT + f];
                const float v = nums[r * NNUM + f];
                const ulonglong2 tv = __ldg((const ulonglong2*)&Tf[c * 128 + 4 * j4]);
                const u64p v2 = pk2(v, v);
                acc[s].x = fma2(v2, pv.x, add2(acc[s].x, tv.x));
                acc[s].y = fma2(v2, pv.y, add2(acc[s].y, tv.y));
            }
        }
        // ---- LN0 (warp-wide) + store normalized to S ----
        #pragma unroll
        for (int s = 0; s < 16; s++) {
            const int r = 8 * s + w;
            float ax, ay, az, aw;
            upk2(acc[s].x, ax, ay);
            upk2(acc[s].y, az, aw);
            float s1 = ax + ay + az + aw;
            float s2 = ax * ax + ay * ay + az * az + aw * aw;
            #pragma unroll
            for (int o = 16; o > 0; o >>= 1) {
                s1 += __shfl_xor_sync(0xffffffffu, s1, o);
                s2 += __shfl_xor_sync(0xffffffffu, s2, o);
            }
            float mu = s1 * (1.f / 128.f);
            float var = s2 * (1.f / 128.f) - mu * mu;
            float inv = rsqrtf(var + LN_EPS);
            *(float4*)&S[r * SP + 4 * j4] =
                make_float4((ax - mu) * inv, (ay - mu) * inv, (az - mu) * inv, (aw - mu) * inv);
        }
    }
    __syncthreads();

    // thread tile: 8 rows (8*tr..) x 8 cols (8*tc..), cols as 4 packed pairs
    const int tr = t >> 4;
    const int tc = t & 15;
    u64p z2[8][4];

    // ---- GEMM1 (packed): z1 = zn0 @ M1 + c1 ----
    {
        const ulonglong2 cb0 = *(const ulonglong2*)&g_c1[8 * tc];
        const ulonglong2 cb1 = *(const ulonglong2*)&g_c1[8 * tc + 4];
        #pragma unroll
        for (int i = 0; i < 8; i++) {
            z2[i][0] = cb0.x; z2[i][1] = cb0.y; z2[i][2] = cb1.x; z2[i][3] = cb1.y;
        }
        for (int k = 0; k < 128; k += 4) {
            float4 a4[8];
            #pragma unroll
            for (int i = 0; i < 8; i++) a4[i] = *(const float4*)&S[(8 * tr + i) * SP + k];
            #pragma unroll
            for (int kk = 0; kk < 4; kk++) {
                const ulonglong2 b0 = __ldg((const ulonglong2*)&g_M1[(k + kk) * 128 + 8 * tc]);
                const ulonglong2 b1v = __ldg((const ulonglong2*)&g_M1[(k + kk) * 128 + 8 * tc + 4]);
                #pragma unroll
                for (int i = 0; i < 8; i++) {
                    const float a = (kk == 0) ? a4[i].x : (kk == 1) ? a4[i].y
                                  : (kk == 2) ? a4[i].z : a4[i].w;
                    const u64p a2 = pk2(a, a);
                    z2[i][0] = fma2(a2, b0.x, z2[i][0]);
                    z2[i][1] = fma2(a2, b0.y, z2[i][1]);
                    z2[i][2] = fma2(a2, b1v.x, z2[i][2]);
                    z2[i][3] = fma2(a2, b1v.y, z2[i][3]);
                }
            }
        }
    }

    // ---- LN1 + write zn1 back to S ----
    {
        #pragma unroll
        for (int i = 0; i < 8; i++) {
            float zv[8];
            upk2(z2[i][0], zv[0], zv[1]);
            upk2(z2[i][1], zv[2], zv[3]);
            upk2(z2[i][2], zv[4], zv[5]);
            upk2(z2[i][3], zv[6], zv[7]);
            float s1 = 0.f, s2 = 0.f;
            #pragma unroll
            for (int jj = 0; jj < 8; jj++) { s1 += zv[jj]; s2 += zv[jj] * zv[jj]; }
            #pragma unroll
            for (int o = 8; o > 0; o >>= 1) {
                s1 += __shfl_xor_sync(0xffffffffu, s1, o);
                s2 += __shfl_xor_sync(0xffffffffu, s2, o);
            }
            float mu = s1 * (1.f / 128.f);
            float var = s2 * (1.f / 128.f) - mu * mu;
            float inv = rsqrtf(var + LN_EPS);
            #pragma unroll
            for (int jj = 0; jj < 8; jj++) zv[jj] = (zv[jj] - mu) * inv;
            z2[i][0] = pk2(zv[0], zv[1]);
            z2[i][1] = pk2(zv[2], zv[3]);
            z2[i][2] = pk2(zv[4], zv[5]);
            z2[i][3] = pk2(zv[6], zv[7]);
        }
        __syncthreads();  // all GEMM1 reads of S done before overwrite
        #pragma unroll
        for (int i = 0; i < 8; i++) {
            *(ulonglong2*)&S[(8 * tr + i) * SP + 8 * tc] = make_ulonglong2(z2[i][0], z2[i][1]);
            *(ulonglong2*)&S[(8 * tr + i) * SP + 8 * tc + 4] = make_ulonglong2(z2[i][2], z2[i][3]);
        }
        __syncthreads();
    }

    // ---- GEMM2 (packed): out = zn1 @ Mo + co ----
    {
        const ulonglong2 cb0 = *(const ulonglong2*)&g_co[8 * tc];
        const ulonglong2 cb1 = *(const ulonglong2*)&g_co[8 * tc + 4];
        #pragma unroll
        for (int i = 0; i < 8; i++) {
            z2[i][0] = cb0.x; z2[i][1] = cb0.y; z2[i][2] = cb1.x; z2[i][3] = cb1.y;
        }
        for (int k = 0; k < 128; k += 4) {
            float4 a4[8];
            #pragma unroll
            for (int i = 0; i < 8; i++) a4[i] = *(const float4*)&S[(8 * tr + i) * SP + k];
            #pragma unroll
            for (int kk = 0; kk < 4; kk++) {
                const ulonglong2 b0 = __ldg((const ulonglong2*)&g_Mo[(k + kk) * 128 + 8 * tc]);
                const ulonglong2 b1v = __ldg((const ulonglong2*)&g_Mo[(k + kk) * 128 + 8 * tc + 4]);
                #pragma unroll
                for (int i = 0; i < 8; i++) {
                    const float a = (kk == 0) ? a4[i].x : (kk == 1) ? a4[i].y
                                  : (kk == 2) ? a4[i].z : a4[i].w;
                    const u64p a2 = pk2(a, a);
                    z2[i][0] = fma2(a2, b0.x, z2[i][0]);
                    z2[i][1] = fma2(a2, b0.y, z2[i][1]);
                    z2[i][2] = fma2(a2, b1v.x, z2[i][2]);
                    z2[i][3] = fma2(a2, b1v.y, z2[i][3]);
                }
            }
        }
        #pragma unroll
        for (int i = 0; i < 8; i++) {
            int gr = rowbase + 8 * tr + i;
            if (gr < nrows) {
                *(ulonglong2*)&out[(size_t)gr * 128 + 8 * tc] = make_ulonglong2(z2[i][0], z2[i][1]);
                *(ulonglong2*)&out[(size_t)gr * 128 + 8 * tc + 4] = make_ulonglong2(z2[i][2], z2[i][3]);
            }
        }
    }
}

// ---------------------------------------------------------------------------
extern "C" void kernel_launch(void* const* d_in, const int* in_sizes, int n_in,
                              void* d_out, int out_size) {
    const float* x     = (const float*)d_in[0];
    const float* emb   = (const float*)d_in[1];
    const float* W_num = (const float*)d_in[2];
    const float* b_num = (const float*)d_in[3];
    const float* W_in  = (const float*)d_in[4];
    const float* b_in  = (const float*)d_in[5];
    const float* W1    = (const float*)d_in[6];
    const float* b1    = (const float*)d_in[7];
    const float* W2    = (const float*)d_in[8];
    const float* b2    = (const float*)d_in[9];
    const float* ln_g  = (const float*)d_in[10];
    const float* ln_b  = (const float*)d_in[11];
    const float* W_out = (const float*)d_in[12];
    const float* b_out = (const float*)d_in[13];
    float* out = (float*)d_out;

    int nrows = in_sizes[0] / 40;
    int ntiles = (nrows + TROWS - 1) / TROWS;

    cudaFuncSetAttribute(main_kernel, cudaFuncAttributeMaxDynamicSharedMemorySize, SMEM_BYTES);

    float *pA, *pWfold, *pB1;
    cudaGetSymbolAddress((void**)&pA, g_A);
    cudaGetSymbolAddress((void**)&pWfold, g_Wfold);
    cudaGetSymbolAddress((void**)&pB1, g_B1);

    // precompute chain (graph-ordered on default stream)
    sgemm32<<<dim3(40, 8), 256>>>(W_in, W1, pA, 1280, 256, 128);
    sgemm32<<<dim3(40, 4), 256>>>(pA, W2, pWfold, 1280, 128, 256);
    sgemm32<<<dim3(4, 4), 256>>>(W1 + 128 * 256, W2 + 256 * 128, pB1, 128, 128, 256);
    build_T<<<NCAT * 50, 128>>>(emb);
    build_P<<<NNUM, 128>>>(W_num);
    scaleM<<<128, 128>>>(ln_g, W_out);
    build_biases<<<1, 128>>>(b_num, b_in, W1, b1, W2, b2, ln_b, W_out, b_out);

    main_kernel<<<ntiles, 256, SMEM_BYTES>>>(x, out, nrows);
}